// round 2
// baseline (speedup 1.0000x reference)
#include <cuda_runtime.h>

#define NNODES 100000
#define NEDGES 1600000
#define F 128
#define SCAN_T 1024
#define NSCAN ((NNODES + SCAN_T - 1) / SCAN_T)   // 98

typedef unsigned long long u64;

// ---------------- scratch (static __device__, no allocs) ----------------
__device__ int   g_deg[NNODES];
__device__ float g_invdeg[NNODES];
__device__ int   g_rowptr[NNODES + 1];
__device__ int   g_cursor[NNODES];
__device__ int   g_csrsrc[NEDGES];
__device__ int   g_partials[NSCAN];
__device__ int   g_scanbuf[NNODES];
__device__ float g_h0[NNODES * F];
__device__ float g_h1[NNODES * F];
__device__ float g_mean[NNODES * F];
__device__ float g_A[NNODES * F];
__device__ float g_B[NNODES * F];

// ---------------- CSR build ----------------
__global__ void k_zero_deg() {
    int i = blockIdx.x * blockDim.x + threadIdx.x;
    if (i < NNODES) g_deg[i] = 0;
}

__global__ void k_hist(const int* __restrict__ dst) {
    int e = blockIdx.x * blockDim.x + threadIdx.x;
    if (e < NEDGES) atomicAdd(&g_deg[dst[e]], 1);
}

__global__ void k_scan1() {
    __shared__ int sd[SCAN_T];
    int t = threadIdx.x;
    int i = blockIdx.x * SCAN_T + t;
    int v = (i < NNODES) ? g_deg[i] : 0;
    sd[t] = v;
    __syncthreads();
    for (int off = 1; off < SCAN_T; off <<= 1) {
        int add = (t >= off) ? sd[t - off] : 0;
        __syncthreads();
        sd[t] += add;
        __syncthreads();
    }
    if (i < NNODES) g_scanbuf[i] = sd[t];
    if (t == SCAN_T - 1) g_partials[blockIdx.x] = sd[t];
}

__global__ void k_scan2() {
    if (threadIdx.x == 0) {
        int run = 0;
        for (int b = 0; b < NSCAN; b++) {
            int p = g_partials[b];
            g_partials[b] = run;
            run += p;
        }
    }
}

__global__ void k_scan3() {
    int i = blockIdx.x * blockDim.x + threadIdx.x;
    if (i < NNODES) {
        int incl = g_scanbuf[i] + g_partials[i >> 10];
        int d = g_deg[i];
        int excl = incl - d;
        g_rowptr[i] = excl;
        g_cursor[i] = excl;
        g_invdeg[i] = 1.0f / fmaxf((float)d, 1.0f);
        if (i == 0) g_rowptr[NNODES] = NEDGES;
    }
}

__global__ void k_scatter(const int* __restrict__ src, const int* __restrict__ dst) {
    int e = blockIdx.x * blockDim.x + threadIdx.x;
    if (e < NEDGES) {
        int pos = atomicAdd(&g_cursor[dst[e]], 1);
        g_csrsrc[pos] = src[e];
    }
}

// ---------------- mean aggregation (one warp per dst node, 4-deep MLP) ----------------
__global__ void __launch_bounds__(256) k_aggmean(const float* __restrict__ h) {
    int w    = (blockIdx.x * blockDim.x + threadIdx.x) >> 5;
    int lane = threadIdx.x & 31;
    if (w >= NNODES) return;
    int beg = g_rowptr[w], end = g_rowptr[w + 1];
    int f0 = lane * 4;
    float4 acc = make_float4(0.f, 0.f, 0.f, 0.f);
    for (int i = beg; i < end; i += 32) {
        int n = min(32, end - i);
        int sidx = (lane < n) ? g_csrsrc[i + lane] : 0;
        int j = 0;
        for (; j + 4 <= n; j += 4) {
            int s0 = __shfl_sync(0xffffffffu, sidx, j + 0);
            int s1 = __shfl_sync(0xffffffffu, sidx, j + 1);
            int s2 = __shfl_sync(0xffffffffu, sidx, j + 2);
            int s3 = __shfl_sync(0xffffffffu, sidx, j + 3);
            float4 v0 = *reinterpret_cast<const float4*>(h + s0 * F + f0);
            float4 v1 = *reinterpret_cast<const float4*>(h + s1 * F + f0);
            float4 v2 = *reinterpret_cast<const float4*>(h + s2 * F + f0);
            float4 v3 = *reinterpret_cast<const float4*>(h + s3 * F + f0);
            acc.x += v0.x + v1.x + v2.x + v3.x;
            acc.y += v0.y + v1.y + v2.y + v3.y;
            acc.z += v0.z + v1.z + v2.z + v3.z;
            acc.w += v0.w + v1.w + v2.w + v3.w;
        }
        for (; j < n; j++) {
            int s = __shfl_sync(0xffffffffu, sidx, j);
            float4 v = *reinterpret_cast<const float4*>(h + s * F + f0);
            acc.x += v.x; acc.y += v.y; acc.z += v.z; acc.w += v.w;
        }
    }
    float sc = g_invdeg[w];
    acc.x *= sc; acc.y *= sc; acc.z *= sc; acc.w *= sc;
    *reinterpret_cast<float4*>(g_mean + w * F + f0) = acc;
}

// ---------------- packed f32x2 helpers ----------------
__device__ __forceinline__ void fma2(u64& d, u64 a, u64 b) {
    asm("fma.rn.f32x2 %0, %1, %2, %0;" : "+l"(d) : "l"(a), "l"(b));
}
__device__ __forceinline__ u64 dup_f32(float x) {
    unsigned u = __float_as_uint(x);
    return (u64)u | ((u64)u << 32);
}
__device__ __forceinline__ float lo_f32(u64 p) { return __uint_as_float((unsigned)p); }
__device__ __forceinline__ float hi_f32(u64 p) { return __uint_as_float((unsigned)(p >> 32)); }

// ---------------- fused GEMM with packed f32x2 FMAs ----------------
// out = X1@W1 (+ g_mean@W2) (+bias) (+leaky)
// M x 128 @ 128 x 128, BM=128 BN=128 BK=16, 256 threads, TM=8 TN=8
// A tiles stored in SMEM as duplicated (a,a) u64 pairs -> inner loop has zero packing.
template <bool HAS2, bool LEAKY>
__global__ void __launch_bounds__(256) gemm128(
    const float* __restrict__ X1, const float* __restrict__ W1,
    const float* __restrict__ W2, const float* __restrict__ bias,
    float* __restrict__ out, int M)
{
    __shared__ u64   As1[16][128];                       // 16 KB
    __shared__ u64   As2[HAS2 ? 16 : 1][HAS2 ? 128 : 1]; // 16 KB (or 8 B)
    __shared__ float Ws1[16][128];                       // 8 KB
    __shared__ float Ws2[HAS2 ? 16 : 1][HAS2 ? 128 : 1]; // 8 KB (or 4 B)

    const int tid = threadIdx.x;
    const int tr = tid >> 4;      // 0..15 (row group)
    const int tc = tid & 15;      // 0..15 (col group)
    const int rowBase = blockIdx.x * 128;

    u64 acc[8][4];
#pragma unroll
    for (int i = 0; i < 8; i++)
#pragma unroll
        for (int j = 0; j < 4; j++) acc[i][j] = 0ull;

    for (int k0 = 0; k0 < 128; k0 += 16) {
#pragma unroll
        for (int q = 0; q < 2; q++) {
            int idx = tid * 2 + q;            // 0..511
            // A tiles: r = row in block, kc = k sub-offset
            int r  = idx >> 2;
            int kc = (idx & 3) * 4;
            int grow = rowBase + r;
            float4 v1 = make_float4(0.f, 0.f, 0.f, 0.f);
            float4 v2 = make_float4(0.f, 0.f, 0.f, 0.f);
            if (grow < M) {
                v1 = *reinterpret_cast<const float4*>(X1 + grow * F + k0 + kc);
                if (HAS2)
                    v2 = *reinterpret_cast<const float4*>(g_mean + grow * F + k0 + kc);
            }
            As1[kc + 0][r] = dup_f32(v1.x); As1[kc + 1][r] = dup_f32(v1.y);
            As1[kc + 2][r] = dup_f32(v1.z); As1[kc + 3][r] = dup_f32(v1.w);
            if (HAS2) {
                As2[kc + 0][r] = dup_f32(v2.x); As2[kc + 1][r] = dup_f32(v2.y);
                As2[kc + 2][r] = dup_f32(v2.z); As2[kc + 3][r] = dup_f32(v2.w);
            }
            // W tiles
            int kk = idx >> 5;
            int c  = (idx & 31) * 4;
            *reinterpret_cast<float4*>(&Ws1[kk][c]) =
                *reinterpret_cast<const float4*>(W1 + (k0 + kk) * F + c);
            if (HAS2)
                *reinterpret_cast<float4*>(&Ws2[kk][c]) =
                    *reinterpret_cast<const float4*>(W2 + (k0 + kk) * F + c);
        }
        __syncthreads();

#pragma unroll
        for (int kk = 0; kk < 16; kk++) {
            {
                u64 a1[8];
#pragma unroll
                for (int t = 0; t < 4; t++)
                    *reinterpret_cast<ulonglong2*>(&a1[t * 2]) =
                        *reinterpret_cast<const ulonglong2*>(&As1[kk][tr * 8 + t * 2]);
                u64 wp[4];
                const u64* w1p = reinterpret_cast<const u64*>(&Ws1[kk][tc * 8]);
                *reinterpret_cast<ulonglong2*>(&wp[0]) = *reinterpret_cast<const ulonglong2*>(&w1p[0]);
                *reinterpret_cast<ulonglong2*>(&wp[2]) = *reinterpret_cast<const ulonglong2*>(&w1p[2]);
#pragma unroll
                for (int i = 0; i < 8; i++)
#pragma unroll
                    for (int j = 0; j < 4; j++) fma2(acc[i][j], a1[i], wp[j]);
            }
            if (HAS2) {
                u64 a2[8];
#pragma unroll
                for (int t = 0; t < 4; t++)
                    *reinterpret_cast<ulonglong2*>(&a2[t * 2]) =
                        *reinterpret_cast<const ulonglong2*>(&As2[kk][tr * 8 + t * 2]);
                u64 wp[4];
                const u64* w2p = reinterpret_cast<const u64*>(&Ws2[kk][tc * 8]);
                *reinterpret_cast<ulonglong2*>(&wp[0]) = *reinterpret_cast<const ulonglong2*>(&w2p[0]);
                *reinterpret_cast<ulonglong2*>(&wp[2]) = *reinterpret_cast<const ulonglong2*>(&w2p[2]);
#pragma unroll
                for (int i = 0; i < 8; i++)
#pragma unroll
                    for (int j = 0; j < 4; j++) fma2(acc[i][j], a2[i], wp[j]);
            }
        }
        __syncthreads();
    }

    // epilogue
    float bv[8];
#pragma unroll
    for (int j = 0; j < 8; j++) bv[j] = bias ? bias[tc * 8 + j] : 0.f;

#pragma unroll
    for (int i = 0; i < 8; i++) {
        int grow = rowBase + tr * 8 + i;
        if (grow < M) {
            float o[8];
#pragma unroll
            for (int j = 0; j < 4; j++) {
                float v0 = lo_f32(acc[i][j]) + bv[2 * j];
                float v1 = hi_f32(acc[i][j]) + bv[2 * j + 1];
                if (LEAKY) {
                    v0 = (v0 > 0.f) ? v0 : 0.01f * v0;
                    v1 = (v1 > 0.f) ? v1 : 0.01f * v1;
                }
                o[2 * j] = v0; o[2 * j + 1] = v1;
            }
            float* dst = out + grow * F + tc * 8;
            *reinterpret_cast<float4*>(dst)     = *reinterpret_cast<float4*>(&o[0]);
            *reinterpret_cast<float4*>(dst + 4) = *reinterpret_cast<float4*>(&o[4]);
        }
    }
}

// ---------------- edge MLP (one warp per edge) ----------------
__global__ void __launch_bounds__(256) k_edge(
    const int* __restrict__ src, const int* __restrict__ dst,
    const float* __restrict__ efeat, const float* __restrict__ mw1,
    const float* __restrict__ mw2, const float* __restrict__ mb2,
    float* __restrict__ out)
{
    int w    = (blockIdx.x * blockDim.x + threadIdx.x) >> 5;
    int lane = threadIdx.x & 31;
    if (w >= NEDGES) return;
    int s = src[w], d = dst[w];
    float e = efeat[w];
    int f0 = lane * 4;

    float4 a  = *reinterpret_cast<const float4*>(g_A + s * F + f0);
    float4 b  = *reinterpret_cast<const float4*>(g_B + d * F + f0);
    float4 wr = *reinterpret_cast<const float4*>(mw1 + 256 * F + f0);

    float4 hv;
    hv.x = fmaxf(fmaf(e, wr.x, a.x + b.x), 0.f);
    hv.y = fmaxf(fmaf(e, wr.y, a.y + b.y), 0.f);
    hv.z = fmaxf(fmaf(e, wr.z, a.z + b.z), 0.f);
    hv.w = fmaxf(fmaf(e, wr.w, a.w + b.w), 0.f);

    // mw2 is [128][2]
    float4 q0 = *reinterpret_cast<const float4*>(mw2 + f0 * 2);
    float4 q1 = *reinterpret_cast<const float4*>(mw2 + f0 * 2 + 4);
    float p0 = hv.x * q0.x + hv.y * q0.z + hv.z * q1.x + hv.w * q1.z;
    float p1 = hv.x * q0.y + hv.y * q0.w + hv.z * q1.y + hv.w * q1.w;

#pragma unroll
    for (int off = 16; off; off >>= 1) {
        p0 += __shfl_xor_sync(0xffffffffu, p0, off);
        p1 += __shfl_xor_sync(0xffffffffu, p1, off);
    }
    if (lane == 0) {
        out[2 * w]     = p0 + mb2[0];
        out[2 * w + 1] = p1 + mb2[1];
    }
}

// ---------------- launch ----------------
extern "C" void kernel_launch(void* const* d_in, const int* in_sizes, int n_in,
                              void* d_out, int out_size) {
    const float* node = (const float*)d_in[0];
    const float* ef   = (const float*)d_in[1];
    const int*   src  = (const int*)d_in[2];
    const int*   dst  = (const int*)d_in[3];
    const float* ws0 = (const float*)d_in[4];
    const float* wn0 = (const float*)d_in[5];
    const float* b0  = (const float*)d_in[6];
    const float* ws1 = (const float*)d_in[7];
    const float* wn1 = (const float*)d_in[8];
    const float* b1  = (const float*)d_in[9];
    const float* ws2 = (const float*)d_in[10];
    const float* wn2 = (const float*)d_in[11];
    const float* b2  = (const float*)d_in[12];
    const float* mw1 = (const float*)d_in[13];
    const float* mb1 = (const float*)d_in[14];
    const float* mw2 = (const float*)d_in[15];
    const float* mb2 = (const float*)d_in[16];
    float* out = (float*)d_out;

    float *h0, *h1, *pA, *pB;
    cudaGetSymbolAddress((void**)&h0, g_h0);
    cudaGetSymbolAddress((void**)&h1, g_h1);
    cudaGetSymbolAddress((void**)&pA, g_A);
    cudaGetSymbolAddress((void**)&pB, g_B);

    // CSR build (once, reused for all 3 layers)
    k_zero_deg<<<(NNODES + 255) / 256, 256>>>();
    k_hist<<<(NEDGES + 255) / 256, 256>>>(dst);
    k_scan1<<<NSCAN, SCAN_T>>>();
    k_scan2<<<1, 32>>>();
    k_scan3<<<(NNODES + 255) / 256, 256>>>();
    k_scatter<<<(NEDGES + 255) / 256, 256>>>(src, dst);

    const int aggBlocks  = (NNODES * 32 + 255) / 256;
    const int gemmBlocks = (NNODES + 127) / 128;
    const int edgeBlocks = (NEDGES * 32 + 255) / 256;

    // layer 0: node_feats -> h0
    k_aggmean<<<aggBlocks, 256>>>(node);
    gemm128<true, true><<<gemmBlocks, 256>>>(node, ws0, wn0, b0, h0, NNODES);
    // layer 1: h0 -> h1
    k_aggmean<<<aggBlocks, 256>>>(h0);
    gemm128<true, true><<<gemmBlocks, 256>>>(h0, ws1, wn1, b1, h1, NNODES);
    // layer 2: h1 -> h0
    k_aggmean<<<aggBlocks, 256>>>(h1);
    gemm128<true, true><<<gemmBlocks, 256>>>(h1, ws2, wn2, b2, h0, NNODES);

    // node-level precompute of the factored edge MLP:
    // A = h @ mw1[0:128] + mb1 ;  B = h @ mw1[128:256]
    gemm128<false, false><<<gemmBlocks, 256>>>(h0, mw1, nullptr, mb1, pA, NNODES);
    gemm128<false, false><<<gemmBlocks, 256>>>(h0, mw1 + 128 * F, nullptr, nullptr, pB, NNODES);

    // edge MLP
    k_edge<<<edgeBlocks, 256>>>(src, dst, ef, mw1, mw2, mb2, out);
}

// round 3
// speedup vs baseline: 1.0738x; 1.0738x over previous
#include <cuda_runtime.h>
#include <cuda_bf16.h>

#define NNODES 100000
#define NEDGES 1600000
#define F 128
#define SCAN_T 1024
#define NSCAN ((NNODES + SCAN_T - 1) / SCAN_T)   // 98

// ---------------- scratch (static __device__, no allocs) ----------------
__device__ int   g_deg[NNODES];
__device__ float g_invdeg[NNODES];
__device__ int   g_rowptr[NNODES + 1];
__device__ int   g_cursor[NNODES];
__device__ int   g_csrsrc[NEDGES];
__device__ int   g_partials[NSCAN];
__device__ int   g_scanbuf[NNODES];
__device__ float g_h0[NNODES * F];
__device__ float g_h1[NNODES * F];
__device__ float g_mean[NNODES * F];
__device__ float g_A[NNODES * F];
__device__ float g_B[NNODES * F];

// ---------------- CSR build ----------------
__global__ void k_zero_deg() {
    int i = blockIdx.x * blockDim.x + threadIdx.x;
    if (i < NNODES) g_deg[i] = 0;
}

__global__ void k_hist(const int* __restrict__ dst) {
    int e = blockIdx.x * blockDim.x + threadIdx.x;
    if (e < NEDGES) atomicAdd(&g_deg[dst[e]], 1);
}

__global__ void k_scan1() {
    __shared__ int sd[SCAN_T];
    int t = threadIdx.x;
    int i = blockIdx.x * SCAN_T + t;
    int v = (i < NNODES) ? g_deg[i] : 0;
    sd[t] = v;
    __syncthreads();
    for (int off = 1; off < SCAN_T; off <<= 1) {
        int add = (t >= off) ? sd[t - off] : 0;
        __syncthreads();
        sd[t] += add;
        __syncthreads();
    }
    if (i < NNODES) g_scanbuf[i] = sd[t];
    if (t == SCAN_T - 1) g_partials[blockIdx.x] = sd[t];
}

__global__ void k_scan2() {
    if (threadIdx.x == 0) {
        int run = 0;
        for (int b = 0; b < NSCAN; b++) {
            int p = g_partials[b];
            g_partials[b] = run;
            run += p;
        }
    }
}

__global__ void k_scan3() {
    int i = blockIdx.x * blockDim.x + threadIdx.x;
    if (i < NNODES) {
        int incl = g_scanbuf[i] + g_partials[i >> 10];
        int d = g_deg[i];
        int excl = incl - d;
        g_rowptr[i] = excl;
        g_cursor[i] = excl;
        g_invdeg[i] = 1.0f / fmaxf((float)d, 1.0f);
        if (i == 0) g_rowptr[NNODES] = NEDGES;
    }
}

__global__ void k_scatter(const int* __restrict__ src, const int* __restrict__ dst) {
    int e = blockIdx.x * blockDim.x + threadIdx.x;
    if (e < NEDGES) {
        int pos = atomicAdd(&g_cursor[dst[e]], 1);
        g_csrsrc[pos] = src[e];
    }
}

// ---------------- mean aggregation (one warp per dst node, 4-deep MLP) ----------------
__global__ void __launch_bounds__(256) k_aggmean(const float* __restrict__ h) {
    int w    = (blockIdx.x * blockDim.x + threadIdx.x) >> 5;
    int lane = threadIdx.x & 31;
    if (w >= NNODES) return;
    int beg = g_rowptr[w], end = g_rowptr[w + 1];
    int f0 = lane * 4;
    float4 acc = make_float4(0.f, 0.f, 0.f, 0.f);
    for (int i = beg; i < end; i += 32) {
        int n = min(32, end - i);
        int sidx = (lane < n) ? g_csrsrc[i + lane] : 0;
        int j = 0;
        for (; j + 4 <= n; j += 4) {
            int s0 = __shfl_sync(0xffffffffu, sidx, j + 0);
            int s1 = __shfl_sync(0xffffffffu, sidx, j + 1);
            int s2 = __shfl_sync(0xffffffffu, sidx, j + 2);
            int s3 = __shfl_sync(0xffffffffu, sidx, j + 3);
            float4 v0 = *reinterpret_cast<const float4*>(h + s0 * F + f0);
            float4 v1 = *reinterpret_cast<const float4*>(h + s1 * F + f0);
            float4 v2 = *reinterpret_cast<const float4*>(h + s2 * F + f0);
            float4 v3 = *reinterpret_cast<const float4*>(h + s3 * F + f0);
            acc.x += v0.x + v1.x + v2.x + v3.x;
            acc.y += v0.y + v1.y + v2.y + v3.y;
            acc.z += v0.z + v1.z + v2.z + v3.z;
            acc.w += v0.w + v1.w + v2.w + v3.w;
        }
        for (; j < n; j++) {
            int s = __shfl_sync(0xffffffffu, sidx, j);
            float4 v = *reinterpret_cast<const float4*>(h + s * F + f0);
            acc.x += v.x; acc.y += v.y; acc.z += v.z; acc.w += v.w;
        }
    }
    float sc = g_invdeg[w];
    acc.x *= sc; acc.y *= sc; acc.z *= sc; acc.w *= sc;
    *reinterpret_cast<float4*>(g_mean + w * F + f0) = acc;
}

// ---------------- tensor-core GEMM with bf16 two-term split ----------------
// out = X1@W1 (+ X2@W2) (+bias) (+leaky relu)
// Block tile: BM=128, BN=128, K handled in BK=32 chunks. 256 threads = 8 warps
// (2x4 warp grid, warp tile 64x32). Each fp32 operand is split x = x_hi + x_lo
// (both bf16); 3 mma passes: hi*hi + hi*lo + lo*hi (fp32 accumulate).

__device__ __forceinline__ void mma_bf16(float* c, const unsigned* a, const unsigned* b) {
    asm volatile(
        "mma.sync.aligned.m16n8k16.row.col.f32.bf16.bf16.f32 "
        "{%0,%1,%2,%3}, {%4,%5,%6,%7}, {%8,%9}, {%0,%1,%2,%3};"
        : "+f"(c[0]), "+f"(c[1]), "+f"(c[2]), "+f"(c[3])
        : "r"(a[0]), "r"(a[1]), "r"(a[2]), "r"(a[3]), "r"(b[0]), "r"(b[1]));
}

__device__ __forceinline__ void split_bf16(float v, __nv_bfloat16& h, __nv_bfloat16& l) {
    h = __float2bfloat16_rn(v);
    l = __float2bfloat16_rn(v - __bfloat162float(h));
}

#define SPAD 40   // bf16 row stride: 80B = 20 banks/row -> conflict-free frag loads

template <bool HAS2, bool LEAKY>
__global__ void __launch_bounds__(256) gemm_tc(
    const float* __restrict__ X1, const float* __restrict__ W1,
    const float* __restrict__ X2, const float* __restrict__ W2,
    const float* __restrict__ bias, float* __restrict__ out, int M)
{
    __shared__ alignas(16) __nv_bfloat16 sAh[128][SPAD];
    __shared__ alignas(16) __nv_bfloat16 sAl[128][SPAD];
    __shared__ alignas(16) __nv_bfloat16 sWh[128][SPAD];   // stored transposed: sW[n][k]
    __shared__ alignas(16) __nv_bfloat16 sWl[128][SPAD];

    const int tid  = threadIdx.x;
    const int lane = tid & 31;
    const int g    = lane >> 2;      // 0..7
    const int tg   = lane & 3;       // 0..3
    const int wm   = (tid >> 5) >> 2;   // 0..1
    const int wn   = (tid >> 5) & 3;    // 0..3
    const int rowBase = blockIdx.x * 128;

    float acc[4][4][4];
#pragma unroll
    for (int mt = 0; mt < 4; mt++)
#pragma unroll
        for (int nt = 0; nt < 4; nt++)
#pragma unroll
            for (int q = 0; q < 4; q++) acc[mt][nt][q] = 0.f;

    const int NCHUNK = HAS2 ? 8 : 4;
    for (int c = 0; c < NCHUNK; c++) {
        const float* Xp = (c < 4) ? X1 : X2;
        const float* Wp = (c < 4) ? W1 : W2;
        const int k0 = (c & 3) * 32;

        // ---- load & split A chunk: 128 rows x 32 k ----
#pragma unroll
        for (int e = tid; e < 1024; e += 256) {
            int row = e >> 3;
            int c4  = (e & 7) << 2;
            int grow = rowBase + row;
            float4 v = make_float4(0.f, 0.f, 0.f, 0.f);
            if (grow < M)
                v = *reinterpret_cast<const float4*>(Xp + grow * F + k0 + c4);
            __nv_bfloat16 h0, l0, h1, l1, h2, l2, h3, l3;
            split_bf16(v.x, h0, l0); split_bf16(v.y, h1, l1);
            split_bf16(v.z, h2, l2); split_bf16(v.w, h3, l3);
            *reinterpret_cast<__nv_bfloat162*>(&sAh[row][c4])     = __nv_bfloat162(h0, h1);
            *reinterpret_cast<__nv_bfloat162*>(&sAh[row][c4 + 2]) = __nv_bfloat162(h2, h3);
            *reinterpret_cast<__nv_bfloat162*>(&sAl[row][c4])     = __nv_bfloat162(l0, l1);
            *reinterpret_cast<__nv_bfloat162*>(&sAl[row][c4 + 2]) = __nv_bfloat162(l2, l3);
        }
        // ---- load & split W chunk: 32 k-rows x 128 n, store transposed [n][k] ----
#pragma unroll
        for (int e = tid; e < 1024; e += 256) {
            int k  = e >> 5;
            int n4 = (e & 31) << 2;
            float4 w = *reinterpret_cast<const float4*>(Wp + (k0 + k) * F + n4);
            float vv[4] = {w.x, w.y, w.z, w.w};
#pragma unroll
            for (int j = 0; j < 4; j++) {
                __nv_bfloat16 h, l;
                split_bf16(vv[j], h, l);
                sWh[n4 + j][k] = h;
                sWl[n4 + j][k] = l;
            }
        }
        __syncthreads();

        // ---- compute: 2 k16-steps per chunk, 3 split passes each ----
#pragma unroll
        for (int kk = 0; kk < 2; kk++) {
            const int kb = kk * 16 + tg * 2;
            unsigned bh[4][2], bl[4][2];
#pragma unroll
            for (int nt = 0; nt < 4; nt++) {
                const int n0 = wn * 32 + nt * 8 + g;
                bh[nt][0] = *reinterpret_cast<const unsigned*>(&sWh[n0][kb]);
                bh[nt][1] = *reinterpret_cast<const unsigned*>(&sWh[n0][kb + 8]);
                bl[nt][0] = *reinterpret_cast<const unsigned*>(&sWl[n0][kb]);
                bl[nt][1] = *reinterpret_cast<const unsigned*>(&sWl[n0][kb + 8]);
            }
#pragma unroll
            for (int mt = 0; mt < 4; mt++) {
                const int r0 = wm * 64 + mt * 16 + g;
                unsigned ah[4], al[4];
                ah[0] = *reinterpret_cast<const unsigned*>(&sAh[r0][kb]);
                ah[1] = *reinterpret_cast<const unsigned*>(&sAh[r0 + 8][kb]);
                ah[2] = *reinterpret_cast<const unsigned*>(&sAh[r0][kb + 8]);
                ah[3] = *reinterpret_cast<const unsigned*>(&sAh[r0 + 8][kb + 8]);
#pragma unroll
                for (int nt = 0; nt < 4; nt++) mma_bf16(acc[mt][nt], ah, bh[nt]);
#pragma unroll
                for (int nt = 0; nt < 4; nt++) mma_bf16(acc[mt][nt], ah, bl[nt]);
                al[0] = *reinterpret_cast<const unsigned*>(&sAl[r0][kb]);
                al[1] = *reinterpret_cast<const unsigned*>(&sAl[r0 + 8][kb]);
                al[2] = *reinterpret_cast<const unsigned*>(&sAl[r0][kb + 8]);
                al[3] = *reinterpret_cast<const unsigned*>(&sAl[r0 + 8][kb + 8]);
#pragma unroll
                for (int nt = 0; nt < 4; nt++) mma_bf16(acc[mt][nt], al, bh[nt]);
            }
        }
        __syncthreads();
    }

    // ---- epilogue ----
#pragma unroll
    for (int nt = 0; nt < 4; nt++) {
        const int col = wn * 32 + nt * 8 + tg * 2;
        const float b0v = bias ? bias[col]     : 0.f;
        const float b1v = bias ? bias[col + 1] : 0.f;
#pragma unroll
        for (int mt = 0; mt < 4; mt++) {
            const int r0 = rowBase + wm * 64 + mt * 16 + g;
            float v0 = acc[mt][nt][0] + b0v;
            float v1 = acc[mt][nt][1] + b1v;
            float v2 = acc[mt][nt][2] + b0v;
            float v3 = acc[mt][nt][3] + b1v;
            if (LEAKY) {
                v0 = (v0 > 0.f) ? v0 : 0.01f * v0;
                v1 = (v1 > 0.f) ? v1 : 0.01f * v1;
                v2 = (v2 > 0.f) ? v2 : 0.01f * v2;
                v3 = (v3 > 0.f) ? v3 : 0.01f * v3;
            }
            if (r0 < M)
                *reinterpret_cast<float2*>(out + r0 * F + col) = make_float2(v0, v1);
            if (r0 + 8 < M)
                *reinterpret_cast<float2*>(out + (r0 + 8) * F + col) = make_float2(v2, v3);
        }
    }
}

// ---------------- edge MLP (one warp per edge) ----------------
__global__ void __launch_bounds__(256) k_edge(
    const int* __restrict__ src, const int* __restrict__ dst,
    const float* __restrict__ efeat, const float* __restrict__ mw1,
    const float* __restrict__ mw2, const float* __restrict__ mb2,
    float* __restrict__ out)
{
    int w    = (blockIdx.x * blockDim.x + threadIdx.x) >> 5;
    int lane = threadIdx.x & 31;
    if (w >= NEDGES) return;
    int s = src[w], d = dst[w];
    float e = efeat[w];
    int f0 = lane * 4;

    float4 a  = *reinterpret_cast<const float4*>(g_A + s * F + f0);
    float4 b  = *reinterpret_cast<const float4*>(g_B + d * F + f0);
    float4 wr = *reinterpret_cast<const float4*>(mw1 + 256 * F + f0);

    float4 hv;
    hv.x = fmaxf(fmaf(e, wr.x, a.x + b.x), 0.f);
    hv.y = fmaxf(fmaf(e, wr.y, a.y + b.y), 0.f);
    hv.z = fmaxf(fmaf(e, wr.z, a.z + b.z), 0.f);
    hv.w = fmaxf(fmaf(e, wr.w, a.w + b.w), 0.f);

    // mw2 is [128][2]
    float4 q0 = *reinterpret_cast<const float4*>(mw2 + f0 * 2);
    float4 q1 = *reinterpret_cast<const float4*>(mw2 + f0 * 2 + 4);
    float p0 = hv.x * q0.x + hv.y * q0.z + hv.z * q1.x + hv.w * q1.z;
    float p1 = hv.x * q0.y + hv.y * q0.w + hv.z * q1.y + hv.w * q1.w;

#pragma unroll
    for (int off = 16; off; off >>= 1) {
        p0 += __shfl_xor_sync(0xffffffffu, p0, off);
        p1 += __shfl_xor_sync(0xffffffffu, p1, off);
    }
    if (lane == 0) {
        out[2 * w]     = p0 + mb2[0];
        out[2 * w + 1] = p1 + mb2[1];
    }
}

// ---------------- launch ----------------
extern "C" void kernel_launch(void* const* d_in, const int* in_sizes, int n_in,
                              void* d_out, int out_size) {
    const float* node = (const float*)d_in[0];
    const float* ef   = (const float*)d_in[1];
    const int*   src  = (const int*)d_in[2];
    const int*   dst  = (const int*)d_in[3];
    const float* ws0 = (const float*)d_in[4];
    const float* wn0 = (const float*)d_in[5];
    const float* b0  = (const float*)d_in[6];
    const float* ws1 = (const float*)d_in[7];
    const float* wn1 = (const float*)d_in[8];
    const float* b1  = (const float*)d_in[9];
    const float* ws2 = (const float*)d_in[10];
    const float* wn2 = (const float*)d_in[11];
    const float* b2  = (const float*)d_in[12];
    const float* mw1 = (const float*)d_in[13];
    const float* mb1 = (const float*)d_in[14];
    const float* mw2 = (const float*)d_in[15];
    const float* mb2 = (const float*)d_in[16];
    float* out = (float*)d_out;

    float *h0, *h1, *pA, *pB, *pm;
    cudaGetSymbolAddress((void**)&h0, g_h0);
    cudaGetSymbolAddress((void**)&h1, g_h1);
    cudaGetSymbolAddress((void**)&pA, g_A);
    cudaGetSymbolAddress((void**)&pB, g_B);
    cudaGetSymbolAddress((void**)&pm, g_mean);

    // CSR build (once, reused for all 3 layers)
    k_zero_deg<<<(NNODES + 255) / 256, 256>>>();
    k_hist<<<(NEDGES + 255) / 256, 256>>>(dst);
    k_scan1<<<NSCAN, SCAN_T>>>();
    k_scan2<<<1, 32>>>();
    k_scan3<<<(NNODES + 255) / 256, 256>>>();
    k_scatter<<<(NEDGES + 255) / 256, 256>>>(src, dst);

    const int aggBlocks  = (NNODES * 32 + 255) / 256;
    const int gemmBlocks = (NNODES + 127) / 128;
    const int edgeBlocks = (NEDGES * 32 + 255) / 256;

    // layer 0: node_feats -> h0
    k_aggmean<<<aggBlocks, 256>>>(node);
    gemm_tc<true, true><<<gemmBlocks, 256>>>(node, ws0, pm, wn0, b0, h0, NNODES);
    // layer 1: h0 -> h1
    k_aggmean<<<aggBlocks, 256>>>(h0);
    gemm_tc<true, true><<<gemmBlocks, 256>>>(h0, ws1, pm, wn1, b1, h1, NNODES);
    // layer 2: h1 -> h0
    k_aggmean<<<aggBlocks, 256>>>(h1);
    gemm_tc<true, true><<<gemmBlocks, 256>>>(h1, ws2, pm, wn2, b2, h0, NNODES);

    // node-level precompute of the factored edge MLP:
    // A = h @ mw1[0:128] + mb1 ;  B = h @ mw1[128:256]
    gemm_tc<false, false><<<gemmBlocks, 256>>>(h0, mw1, nullptr, nullptr, mb1, pA, NNODES);
    gemm_tc<false, false><<<gemmBlocks, 256>>>(h0, mw1 + 128 * F, nullptr, nullptr, nullptr, pB, NNODES);

    // edge MLP
    k_edge<<<edgeBlocks, 256>>>(src, dst, ef, mw1, mw2, mb2, out);
}